// round 14
// baseline (speedup 1.0000x reference)
#include <cuda_runtime.h>
#include <cuda_fp16.h>
#include <cstdint>

#define N_NODES 500000
#define N_EDGES 5000000
#define N_GRAPHS 5000
#define FEAT 7
#define STATE 16
#define ROUNDS 4

#define SCAN_CHUNK 1024
#define SCAN_T 256
#define SCAN_NB ((N_NODES + SCAN_CHUNK - 1) / SCAN_CHUNK)   // 489

// ---- scratch (__device__ globals; no allocs allowed) ----
__device__ __half g_state[N_NODES * STATE];    // fp16 state (16 MB)
__device__ __half g_msg_a[N_NODES * STATE];
__device__ __half g_msg_b[N_NODES * STATE];
__device__ int    g_cnt[N_NODES + 8];
__device__ int    g_excl[N_NODES + 8];
__device__ int    g_bsum[SCAN_NB];
__device__ int    g_ptr[N_NODES + 8];
__device__ unsigned short g_rank[N_EDGES + 8];
__device__ int    g_csr_src[N_EDGES];

// ---- 256-bit load/store helpers (sm_100+) ----
__device__ __forceinline__ void ldg256(const void* p, unsigned int* w) {
    asm volatile("ld.global.nc.v8.b32 {%0,%1,%2,%3,%4,%5,%6,%7}, [%8];"
                 : "=r"(w[0]), "=r"(w[1]), "=r"(w[2]), "=r"(w[3]),
                   "=r"(w[4]), "=r"(w[5]), "=r"(w[6]), "=r"(w[7])
                 : "l"(p));
}
__device__ __forceinline__ void stg256(void* p, const unsigned int* w) {
    asm volatile("st.global.v8.b32 [%0], {%1,%2,%3,%4,%5,%6,%7,%8};"
                 :: "l"(p),
                    "r"(w[0]), "r"(w[1]), "r"(w[2]), "r"(w[3]),
                    "r"(w[4]), "r"(w[5]), "r"(w[6]), "r"(w[7])
                 : "memory");
}

__device__ __forceinline__ void store_h16(__half* dst, const float* m) {
    unsigned int w[8];
#pragma unroll
    for (int v = 0; v < 8; v++) {
        __half2 hh = __floats2half2_rn(m[2 * v], m[2 * v + 1]);
        w[v] = *reinterpret_cast<unsigned int*>(&hh);
    }
    stg256(dst, w);
}

__device__ __forceinline__ void load_h16(const __half* src, float* f) {
    unsigned int w[8];
    ldg256(src, w);
#pragma unroll
    for (int v = 0; v < 8; v++) {
        __half2 hh = *reinterpret_cast<const __half2*>(&w[v]);
        float2 ff = __half22float2(hh);
        f[2 * v] = ff.x;
        f[2 * v + 1] = ff.y;
    }
}

__device__ __forceinline__ void acc_row8(const unsigned int* w, float* acc) {
#pragma unroll
    for (int v = 0; v < 8; v++) {
        __half2 hh = *reinterpret_cast<const __half2*>(&w[v]);
        float2 f = __half22float2(hh);
        acc[2 * v] += f.x;
        acc[2 * v + 1] += f.y;
    }
}

// ================= CSR build =================
__global__ void zero_cnt_kernel() {
    int i4 = (blockIdx.x * blockDim.x + threadIdx.x) * 4;
    if (i4 < N_NODES)
        *reinterpret_cast<int4*>(g_cnt + i4) = make_int4(0, 0, 0, 0);
}

// histogram with rank return -> scatter needs no atomics
__global__ void hist_kernel(const int* __restrict__ ei) {
    int e4 = (blockIdx.x * blockDim.x + threadIdx.x) * 4;
    if (e4 >= N_EDGES) return;
    int4 d = __ldg(reinterpret_cast<const int4*>(ei + N_EDGES + e4));
    ushort4 r;
    r.x = (unsigned short)atomicAdd(&g_cnt[d.x], 1);
    r.y = (unsigned short)atomicAdd(&g_cnt[d.y], 1);
    r.z = (unsigned short)atomicAdd(&g_cnt[d.z], 1);
    r.w = (unsigned short)atomicAdd(&g_cnt[d.w], 1);
    *reinterpret_cast<ushort4*>(g_rank + e4) = r;
}

__global__ void scan1_kernel() {
    __shared__ int sh[SCAN_T];
    int b = blockIdx.x, t = threadIdx.x;
    int base = b * SCAN_CHUNK + t * 4;
    int4 vv = (base < N_NODES) ? *reinterpret_cast<const int4*>(g_cnt + base)
                               : make_int4(0, 0, 0, 0);
    int v[4] = {vv.x, vv.y, vv.z, vv.w};
#pragma unroll
    for (int k = 0; k < 4; k++)
        if (base + k >= N_NODES) v[k] = 0;
    int s = v[0] + v[1] + v[2] + v[3];
    sh[t] = s;
    __syncthreads();
    for (int off = 1; off < SCAN_T; off <<= 1) {
        int x = (t >= off) ? sh[t - off] : 0;
        __syncthreads();
        sh[t] += x;
        __syncthreads();
    }
    int thread_excl = sh[t] - s;
    if (t == SCAN_T - 1) g_bsum[b] = sh[t];
    int4 ev;
    ev.x = thread_excl;
    ev.y = ev.x + v[0];
    ev.z = ev.y + v[1];
    ev.w = ev.z + v[2];
    if (base < N_NODES)
        *reinterpret_cast<int4*>(g_excl + base) = ev;
}

// fused: scan block sums locally (redundant per block), write ptr
__global__ void scan3_kernel() {
    __shared__ int sb[512];
    int b = blockIdx.x, t = threadIdx.x;
    int orig = 0, orig2 = 0;
    if (t < SCAN_NB) orig = g_bsum[t];
    if (t + 256 < SCAN_NB) orig2 = g_bsum[t + 256];
    sb[t] = orig;
    sb[t + 256] = orig2;
    __syncthreads();
    for (int off = 1; off < 512; off <<= 1) {
        int x0 = (t >= off) ? sb[t - off] : 0;
        int x1 = (t + 256 >= off) ? sb[t + 256 - off] : 0;
        __syncthreads();
        sb[t] += x0;
        sb[t + 256] += x1;
        __syncthreads();
    }
    __shared__ int sexcl[512];
    sexcl[t] = sb[t] - orig;
    sexcl[t + 256] = sb[t + 256] - orig2;
    __syncthreads();

    int base = b * SCAN_CHUNK + t * 4;
    if (base < N_NODES) {
        int add = sexcl[base / SCAN_CHUNK];
        int4 e = *reinterpret_cast<const int4*>(g_excl + base);
        *reinterpret_cast<int4*>(g_ptr + base) =
            make_int4(e.x + add, e.y + add, e.z + add, e.w + add);
    }
    if (b == 0 && t == 0) g_ptr[N_NODES] = N_EDGES;
}

// atomic-free scatter: position = ptr[dst] + rank[e]
__global__ void scatter_kernel(const int* __restrict__ ei) {
    int e4 = (blockIdx.x * blockDim.x + threadIdx.x) * 4;
    if (e4 >= N_EDGES) return;
    int4 s = __ldg(reinterpret_cast<const int4*>(ei + e4));
    int4 d = __ldg(reinterpret_cast<const int4*>(ei + N_EDGES + e4));
    ushort4 r = *reinterpret_cast<const ushort4*>(g_rank + e4);
    g_csr_src[__ldg(&g_ptr[d.x]) + (int)r.x] = s.x;
    g_csr_src[__ldg(&g_ptr[d.y]) + (int)r.y] = s.y;
    g_csr_src[__ldg(&g_ptr[d.z]) + (int)r.z] = s.z;
    g_csr_src[__ldg(&g_ptr[d.w]) + (int)r.w] = s.w;
}

// ============ input: state = relu(x@inW+b), msg0 = relu(state@msgW0+b0) ============
__global__ void input_kernel(const float* __restrict__ x,
                             const float* __restrict__ inW,
                             const float* __restrict__ inb,
                             const float* __restrict__ mW,
                             const float* __restrict__ mb,
                             const float* __restrict__ out_b,
                             float* __restrict__ out) {
    __shared__ float sIW[FEAT * STATE];
    __shared__ float sIb[STATE];
    __shared__ float sMW[STATE * STATE];
    __shared__ float sMb[STATE];
    int t = threadIdx.x;
    if (t < FEAT * STATE) sIW[t] = inW[t];
    if (t < STATE) { sIb[t] = inb[t]; sMb[t] = mb[t]; }
    if (t < STATE * STATE) sMW[t] = mW[t];
    __syncthreads();

    int i = blockIdx.x * blockDim.x + t;
    if (i < N_GRAPHS) out[i] = out_b[0];
    if (i >= N_NODES) return;

    float xi[FEAT];
#pragma unroll
    for (int k = 0; k < FEAT; k++) xi[k] = x[(size_t)i * FEAT + k];

    float st[STATE];
#pragma unroll
    for (int j = 0; j < STATE; j++) {
        float acc = sIb[j];
#pragma unroll
        for (int k = 0; k < FEAT; k++) acc = fmaf(xi[k], sIW[k * STATE + j], acc);
        st[j] = fmaxf(acc, 0.f);
    }
    store_h16(g_state + (size_t)i * STATE, st);

    float m[STATE];
#pragma unroll
    for (int j = 0; j < STATE; j++) {
        float acc = sMb[j];
#pragma unroll
        for (int k = 0; k < STATE; k++) acc = fmaf(st[k], sMW[k * STATE + j], acc);
        m[j] = fmaxf(acc, 0.f);
    }
    store_h16(g_msg_a + (size_t)i * STATE, m);
}

// ============ fused round: 1 thread/node, unroll-2 gather, high occupancy ============
__global__ __launch_bounds__(256, 6) void round_kernel(
                             const float* __restrict__ updW,
                             const float* __restrict__ updb,
                             const float* __restrict__ msgW,   // unused if last
                             const float* __restrict__ msgb,
                             const __half* __restrict__ msg_in,
                             __half* __restrict__ msg_out,
                             int last,
                             const int* __restrict__ batch,
                             const float* __restrict__ outW,
                             float* __restrict__ out) {
    __shared__ float sUW[STATE * STATE];
    __shared__ float sMW[STATE * STATE];
    __shared__ float sUb[STATE];
    __shared__ float sMb[STATE];
    __shared__ float sOW[STATE];
    int t = threadIdx.x;
    if (t < STATE * STATE) {
        sUW[t] = updW[t];
        sMW[t] = last ? 0.f : msgW[t];
    }
    if (t < STATE) {
        sUb[t] = updb[t];
        sMb[t] = last ? 0.f : msgb[t];
        sOW[t] = last ? outW[t] : 0.f;
    }
    __syncthreads();

    int node = blockIdx.x * blockDim.x + t;
    if (node >= N_NODES) return;

    int p0 = g_ptr[node];
    int p1 = g_ptr[node + 1];

    float acc[STATE];
#pragma unroll
    for (int k = 0; k < STATE; k++) acc[k] = 0.f;

    int j = p0;
    for (; j + 2 <= p1; j += 2) {
        int s0 = __ldg(&g_csr_src[j + 0]);
        int s1 = __ldg(&g_csr_src[j + 1]);
        unsigned int w0[8], w1[8];
        ldg256(msg_in + (size_t)s0 * STATE, w0);
        ldg256(msg_in + (size_t)s1 * STATE, w1);
        acc_row8(w0, acc);
        acc_row8(w1, acc);
    }
    if (j < p1) {
        int s = __ldg(&g_csr_src[j]);
        unsigned int w[8];
        ldg256(msg_in + (size_t)s * STATE, w);
        acc_row8(w, acc);
    }

    float st[STATE];
    load_h16(g_state + (size_t)node * STATE, st);

#pragma unroll
    for (int jj = 0; jj < STATE; jj++) {
        float u = sUb[jj];
#pragma unroll
        for (int k = 0; k < STATE; k++) u = fmaf(acc[k], sUW[k * STATE + jj], u);
        st[jj] += fmaxf(u, 0.f);
    }

    if (!last) {
        store_h16(g_state + (size_t)node * STATE, st);
        float m[STATE];
#pragma unroll
        for (int jj = 0; jj < STATE; jj++) {
            float a2 = sMb[jj];
#pragma unroll
            for (int k = 0; k < STATE; k++) a2 = fmaf(st[k], sMW[k * STATE + jj], a2);
            m[jj] = fmaxf(a2, 0.f);
        }
        store_h16(msg_out + (size_t)node * STATE, m);
    } else {
        float dot = 0.f;
#pragma unroll
        for (int k = 0; k < STATE; k++) dot = fmaf(st[k], sOW[k], dot);
        atomicAdd(&out[batch[node]], dot);
    }
}

extern "C" void kernel_launch(void* const* d_in, const int* in_sizes, int n_in,
                              void* d_out, int out_size) {
    const float* x     = (const float*)d_in[0];
    const int*   ei    = (const int*)d_in[1];
    const int*   batch = (const int*)d_in[2];
    const float* in_W  = (const float*)d_in[3];
    const float* in_b  = (const float*)d_in[4];
    const float* msg_W = (const float*)d_in[5];
    const float* msg_b = (const float*)d_in[6];
    const float* upd_W = (const float*)d_in[7];
    const float* upd_b = (const float*)d_in[8];
    const float* out_W = (const float*)d_in[9];
    const float* out_b = (const float*)d_in[10];
    float* out = (float*)d_out;

    static cudaStream_t s2 = nullptr;
    static cudaEvent_t evFork = nullptr, evJoin = nullptr;
    if (s2 == nullptr) {
        cudaStreamCreateWithFlags(&s2, cudaStreamNonBlocking);
        cudaEventCreateWithFlags(&evFork, cudaEventDisableTiming);
        cudaEventCreateWithFlags(&evJoin, cudaEventDisableTiming);
    }

    const int TB = 256;
    int node_blocks  = (N_NODES + TB - 1) / TB;
    int node4_blocks = (N_NODES / 4 + TB - 1) / TB;
    int edge4_blocks = (N_EDGES / 4 + TB - 1) / TB;

    // fork: input (+ out init) runs concurrently with the CSR build
    cudaEventRecord(evFork, 0);
    cudaStreamWaitEvent(s2, evFork, 0);
    input_kernel<<<node_blocks, TB, 0, s2>>>(x, in_W, in_b, msg_W, msg_b, out_b, out);
    cudaEventRecord(evJoin, s2);

    // CSR build chain on the main stream
    zero_cnt_kernel<<<node4_blocks, TB>>>();
    hist_kernel<<<edge4_blocks, TB>>>(ei);
    scan1_kernel<<<SCAN_NB, SCAN_T>>>();
    scan3_kernel<<<SCAN_NB, SCAN_T>>>();
    scatter_kernel<<<edge4_blocks, TB>>>(ei);

    cudaStreamWaitEvent(0, evJoin, 0);

    void* pa; void* pb;
    cudaGetSymbolAddress(&pa, g_msg_a);
    cudaGetSymbolAddress(&pb, g_msg_b);
    __half* bufs[2] = {(__half*)pa, (__half*)pb};

    for (int r = 0; r < ROUNDS; r++) {
        int last = (r == ROUNDS - 1);
        const float* mW = last ? msg_W : (msg_W + (r + 1) * STATE * STATE);
        const float* mb = last ? msg_b : (msg_b + (r + 1) * STATE);
        round_kernel<<<node_blocks, TB>>>(
            upd_W + r * STATE * STATE, upd_b + r * STATE,
            mW, mb,
            bufs[r & 1], bufs[(r + 1) & 1],
            last, batch, out_W, out);
    }
}

// round 15
// speedup vs baseline: 1.1174x; 1.1174x over previous
#include <cuda_runtime.h>
#include <cuda_fp16.h>
#include <cstdint>

#define N_NODES 500000
#define N_EDGES 5000000
#define N_GRAPHS 5000
#define FEAT 7
#define STATE 16
#define ROUNDS 4

#define SCAN_CHUNK 1024
#define SCAN_T 256
#define SCAN_NB ((N_NODES + SCAN_CHUNK - 1) / SCAN_CHUNK)   // 489

// ---- scratch (__device__ globals; no allocs allowed) ----
__device__ __half g_state[N_NODES * STATE];    // fp16 state (16 MB)
__device__ __half g_msg_a[N_NODES * STATE];
__device__ __half g_msg_b[N_NODES * STATE];
__device__ int    g_cnt[N_NODES + 8];
__device__ int    g_fill[N_NODES + 8];
__device__ int    g_excl[N_NODES + 8];
__device__ int    g_bsum[SCAN_NB];
__device__ int    g_ptr[N_NODES + 8];
__device__ int    g_csr_src[N_EDGES];

// ---- 256-bit load/store helpers (sm_100+) ----
__device__ __forceinline__ void ldg256(const void* p, unsigned int* w) {
    asm volatile("ld.global.nc.v8.b32 {%0,%1,%2,%3,%4,%5,%6,%7}, [%8];"
                 : "=r"(w[0]), "=r"(w[1]), "=r"(w[2]), "=r"(w[3]),
                   "=r"(w[4]), "=r"(w[5]), "=r"(w[6]), "=r"(w[7])
                 : "l"(p));
}
__device__ __forceinline__ void stg256(void* p, const unsigned int* w) {
    asm volatile("st.global.v8.b32 [%0], {%1,%2,%3,%4,%5,%6,%7,%8};"
                 :: "l"(p),
                    "r"(w[0]), "r"(w[1]), "r"(w[2]), "r"(w[3]),
                    "r"(w[4]), "r"(w[5]), "r"(w[6]), "r"(w[7])
                 : "memory");
}

__device__ __forceinline__ void store_h16(__half* dst, const float* m) {
    unsigned int w[8];
#pragma unroll
    for (int v = 0; v < 8; v++) {
        __half2 hh = __floats2half2_rn(m[2 * v], m[2 * v + 1]);
        w[v] = *reinterpret_cast<unsigned int*>(&hh);
    }
    stg256(dst, w);
}

__device__ __forceinline__ void load_h16(const __half* src, float* f) {
    unsigned int w[8];
    ldg256(src, w);
#pragma unroll
    for (int v = 0; v < 8; v++) {
        __half2 hh = *reinterpret_cast<const __half2*>(&w[v]);
        float2 ff = __half22float2(hh);
        f[2 * v] = ff.x;
        f[2 * v + 1] = ff.y;
    }
}

__device__ __forceinline__ void acc_row8(const unsigned int* w, float* acc) {
#pragma unroll
    for (int v = 0; v < 8; v++) {
        __half2 hh = *reinterpret_cast<const __half2*>(&w[v]);
        float2 f = __half22float2(hh);
        acc[2 * v] += f.x;
        acc[2 * v + 1] += f.y;
    }
}

// ================= CSR build =================
__global__ void zero_cnt_kernel() {
    int i4 = (blockIdx.x * blockDim.x + threadIdx.x) * 4;
    if (i4 < N_NODES)
        *reinterpret_cast<int4*>(g_cnt + i4) = make_int4(0, 0, 0, 0);
}

__global__ void hist_kernel(const int* __restrict__ ei) {
    int e4 = (blockIdx.x * blockDim.x + threadIdx.x) * 4;
    if (e4 >= N_EDGES) return;
    int4 d = __ldg(reinterpret_cast<const int4*>(ei + N_EDGES + e4));
    atomicAdd(&g_cnt[d.x], 1);
    atomicAdd(&g_cnt[d.y], 1);
    atomicAdd(&g_cnt[d.z], 1);
    atomicAdd(&g_cnt[d.w], 1);
}

__global__ void scan1_kernel() {
    __shared__ int sh[SCAN_T];
    int b = blockIdx.x, t = threadIdx.x;
    int base = b * SCAN_CHUNK + t * 4;
    int4 vv = (base < N_NODES) ? *reinterpret_cast<const int4*>(g_cnt + base)
                               : make_int4(0, 0, 0, 0);
    int v[4] = {vv.x, vv.y, vv.z, vv.w};
#pragma unroll
    for (int k = 0; k < 4; k++)
        if (base + k >= N_NODES) v[k] = 0;
    int s = v[0] + v[1] + v[2] + v[3];
    sh[t] = s;
    __syncthreads();
    for (int off = 1; off < SCAN_T; off <<= 1) {
        int x = (t >= off) ? sh[t - off] : 0;
        __syncthreads();
        sh[t] += x;
        __syncthreads();
    }
    int thread_excl = sh[t] - s;
    if (t == SCAN_T - 1) g_bsum[b] = sh[t];
    int4 ev;
    ev.x = thread_excl;
    ev.y = ev.x + v[0];
    ev.z = ev.y + v[1];
    ev.w = ev.z + v[2];
    if (base < N_NODES)
        *reinterpret_cast<int4*>(g_excl + base) = ev;
}

// fused: scan block sums locally (redundant per block), write ptr + fill
__global__ void scan3_kernel() {
    __shared__ int sb[512];
    int b = blockIdx.x, t = threadIdx.x;
    int orig = 0, orig2 = 0;
    if (t < SCAN_NB) orig = g_bsum[t];
    if (t + 256 < SCAN_NB) orig2 = g_bsum[t + 256];
    sb[t] = orig;
    sb[t + 256] = orig2;
    __syncthreads();
    for (int off = 1; off < 512; off <<= 1) {
        int x0 = (t >= off) ? sb[t - off] : 0;
        int x1 = (t + 256 >= off) ? sb[t + 256 - off] : 0;
        __syncthreads();
        sb[t] += x0;
        sb[t + 256] += x1;
        __syncthreads();
    }
    __shared__ int sexcl[512];
    sexcl[t] = sb[t] - orig;
    sexcl[t + 256] = sb[t + 256] - orig2;
    __syncthreads();

    int base = b * SCAN_CHUNK + t * 4;
    if (base < N_NODES) {
        int add = sexcl[base / SCAN_CHUNK];
        int4 e = *reinterpret_cast<const int4*>(g_excl + base);
        int4 p = make_int4(e.x + add, e.y + add, e.z + add, e.w + add);
        *reinterpret_cast<int4*>(g_ptr + base) = p;
        *reinterpret_cast<int4*>(g_fill + base) = p;
    }
    if (b == 0 && t == 0) g_ptr[N_NODES] = N_EDGES;
}

__global__ void scatter_kernel(const int* __restrict__ ei) {
    int e4 = (blockIdx.x * blockDim.x + threadIdx.x) * 4;
    if (e4 >= N_EDGES) return;
    int4 s = __ldg(reinterpret_cast<const int4*>(ei + e4));
    int4 d = __ldg(reinterpret_cast<const int4*>(ei + N_EDGES + e4));
    int p0 = atomicAdd(&g_fill[d.x], 1);
    int p1 = atomicAdd(&g_fill[d.y], 1);
    int p2 = atomicAdd(&g_fill[d.z], 1);
    int p3 = atomicAdd(&g_fill[d.w], 1);
    g_csr_src[p0] = s.x;
    g_csr_src[p1] = s.y;
    g_csr_src[p2] = s.z;
    g_csr_src[p3] = s.w;
}

// ============ input: state = relu(x@inW+b), msg0 = relu(state@msgW0+b0) ============
__global__ void input_kernel(const float* __restrict__ x,
                             const float* __restrict__ inW,
                             const float* __restrict__ inb,
                             const float* __restrict__ mW,
                             const float* __restrict__ mb,
                             const float* __restrict__ out_b,
                             float* __restrict__ out) {
    __shared__ float sIW[FEAT * STATE];
    __shared__ float sIb[STATE];
    __shared__ float sMW[STATE * STATE];
    __shared__ float sMb[STATE];
    int t = threadIdx.x;
    if (t < FEAT * STATE) sIW[t] = inW[t];
    if (t < STATE) { sIb[t] = inb[t]; sMb[t] = mb[t]; }
    if (t < STATE * STATE) sMW[t] = mW[t];
    __syncthreads();

    int i = blockIdx.x * blockDim.x + t;
    if (i < N_GRAPHS) out[i] = out_b[0];
    if (i >= N_NODES) return;

    float xi[FEAT];
#pragma unroll
    for (int k = 0; k < FEAT; k++) xi[k] = x[(size_t)i * FEAT + k];

    float st[STATE];
#pragma unroll
    for (int j = 0; j < STATE; j++) {
        float acc = sIb[j];
#pragma unroll
        for (int k = 0; k < FEAT; k++) acc = fmaf(xi[k], sIW[k * STATE + j], acc);
        st[j] = fmaxf(acc, 0.f);
    }
    store_h16(g_state + (size_t)i * STATE, st);

    float m[STATE];
#pragma unroll
    for (int j = 0; j < STATE; j++) {
        float acc = sMb[j];
#pragma unroll
        for (int k = 0; k < STATE; k++) acc = fmaf(st[k], sMW[k * STATE + j], acc);
        m[j] = fmaxf(acc, 0.f);
    }
    store_h16(g_msg_a + (size_t)i * STATE, m);
}

// ============ fused round: 1 thread/node, 256-bit gathers, fp16 state ============
__global__ __launch_bounds__(256) void round_kernel(
                             const float* __restrict__ updW,
                             const float* __restrict__ updb,
                             const float* __restrict__ msgW,   // unused if last
                             const float* __restrict__ msgb,
                             const __half* __restrict__ msg_in,
                             __half* __restrict__ msg_out,
                             int last,
                             const int* __restrict__ batch,
                             const float* __restrict__ outW,
                             float* __restrict__ out) {
    __shared__ float sUW[STATE * STATE];
    __shared__ float sMW[STATE * STATE];
    __shared__ float sUb[STATE];
    __shared__ float sMb[STATE];
    __shared__ float sOW[STATE];
    int t = threadIdx.x;
    if (t < STATE * STATE) {
        sUW[t] = updW[t];
        sMW[t] = last ? 0.f : msgW[t];
    }
    if (t < STATE) {
        sUb[t] = updb[t];
        sMb[t] = last ? 0.f : msgb[t];
        sOW[t] = last ? outW[t] : 0.f;
    }
    __syncthreads();

    int node = blockIdx.x * blockDim.x + t;
    if (node >= N_NODES) return;

    int p0 = g_ptr[node];
    int p1 = g_ptr[node + 1];

    float acc[STATE];
#pragma unroll
    for (int k = 0; k < STATE; k++) acc[k] = 0.f;

    int j = p0;
    for (; j + 4 <= p1; j += 4) {
        int s0 = __ldg(&g_csr_src[j + 0]);
        int s1 = __ldg(&g_csr_src[j + 1]);
        int s2 = __ldg(&g_csr_src[j + 2]);
        int s3 = __ldg(&g_csr_src[j + 3]);
        unsigned int w0[8], w1[8], w2[8], w3[8];
        ldg256(msg_in + (size_t)s0 * STATE, w0);
        ldg256(msg_in + (size_t)s1 * STATE, w1);
        ldg256(msg_in + (size_t)s2 * STATE, w2);
        ldg256(msg_in + (size_t)s3 * STATE, w3);
        acc_row8(w0, acc);
        acc_row8(w1, acc);
        acc_row8(w2, acc);
        acc_row8(w3, acc);
    }
    for (; j < p1; j++) {
        int s = __ldg(&g_csr_src[j]);
        unsigned int w[8];
        ldg256(msg_in + (size_t)s * STATE, w);
        acc_row8(w, acc);
    }

    // fp16 state load (one 32B op)
    float st[STATE];
    load_h16(g_state + (size_t)node * STATE, st);

    // state += relu(agg @ updW + updb)
#pragma unroll
    for (int jj = 0; jj < STATE; jj++) {
        float u = sUb[jj];
#pragma unroll
        for (int k = 0; k < STATE; k++) u = fmaf(acc[k], sUW[k * STATE + jj], u);
        st[jj] += fmaxf(u, 0.f);
    }

    if (!last) {
        store_h16(g_state + (size_t)node * STATE, st);
        float m[STATE];
#pragma unroll
        for (int jj = 0; jj < STATE; jj++) {
            float a2 = sMb[jj];
#pragma unroll
            for (int k = 0; k < STATE; k++) a2 = fmaf(st[k], sMW[k * STATE + jj], a2);
            m[jj] = fmaxf(a2, 0.f);
        }
        store_h16(msg_out + (size_t)node * STATE, m);
    } else {
        // readout with warp-segmented aggregation (batch is sorted)
        float dot = 0.f;
#pragma unroll
        for (int k = 0; k < STATE; k++) dot = fmaf(st[k], sOW[k], dot);
        int b = batch[node];

        unsigned mask = __activemask();       // active lanes are a prefix
        int cnt = __popc(mask);
        int lane = t & 31;
#pragma unroll
        for (int off = 1; off < 32; off <<= 1) {
            float d2 = __shfl_down_sync(mask, dot, off);
            int b2   = __shfl_down_sync(mask, b, off);
            if (lane + off < cnt && b2 == b) dot += d2;
        }
        int bprev = __shfl_up_sync(mask, b, 1);
        if (lane == 0 || bprev != b)
            atomicAdd(&out[b], dot);
    }
}

extern "C" void kernel_launch(void* const* d_in, const int* in_sizes, int n_in,
                              void* d_out, int out_size) {
    const float* x     = (const float*)d_in[0];
    const int*   ei    = (const int*)d_in[1];
    const int*   batch = (const int*)d_in[2];
    const float* in_W  = (const float*)d_in[3];
    const float* in_b  = (const float*)d_in[4];
    const float* msg_W = (const float*)d_in[5];
    const float* msg_b = (const float*)d_in[6];
    const float* upd_W = (const float*)d_in[7];
    const float* upd_b = (const float*)d_in[8];
    const float* out_W = (const float*)d_in[9];
    const float* out_b = (const float*)d_in[10];
    float* out = (float*)d_out;

    static cudaStream_t s2 = nullptr;
    static cudaEvent_t evFork = nullptr, evJoin = nullptr;
    if (s2 == nullptr) {
        cudaStreamCreateWithFlags(&s2, cudaStreamNonBlocking);
        cudaEventCreateWithFlags(&evFork, cudaEventDisableTiming);
        cudaEventCreateWithFlags(&evJoin, cudaEventDisableTiming);
    }

    const int TB = 256;
    int node_blocks  = (N_NODES + TB - 1) / TB;
    int node4_blocks = (N_NODES / 4 + TB - 1) / TB;
    int edge4_blocks = (N_EDGES / 4 + TB - 1) / TB;

    // fork: input (+ out init) runs concurrently with the CSR build
    cudaEventRecord(evFork, 0);
    cudaStreamWaitEvent(s2, evFork, 0);
    input_kernel<<<node_blocks, TB, 0, s2>>>(x, in_W, in_b, msg_W, msg_b, out_b, out);
    cudaEventRecord(evJoin, s2);

    // CSR build chain on the main stream
    zero_cnt_kernel<<<node4_blocks, TB>>>();
    hist_kernel<<<edge4_blocks, TB>>>(ei);
    scan1_kernel<<<SCAN_NB, SCAN_T>>>();
    scan3_kernel<<<SCAN_NB, SCAN_T>>>();
    scatter_kernel<<<edge4_blocks, TB>>>(ei);

    cudaStreamWaitEvent(0, evJoin, 0);

    void* pa; void* pb;
    cudaGetSymbolAddress(&pa, g_msg_a);
    cudaGetSymbolAddress(&pb, g_msg_b);
    __half* bufs[2] = {(__half*)pa, (__half*)pb};

    for (int r = 0; r < ROUNDS; r++) {
        int last = (r == ROUNDS - 1);
        const float* mW = last ? msg_W : (msg_W + (r + 1) * STATE * STATE);
        const float* mb = last ? msg_b : (msg_b + (r + 1) * STATE);
        round_kernel<<<node_blocks, TB>>>(
            upd_W + r * STATE * STATE, upd_b + r * STATE,
            mW, mb,
            bufs[r & 1], bufs[(r + 1) & 1],
            last, batch, out_W, out);
    }
}

// round 16
// speedup vs baseline: 1.1181x; 1.0007x over previous
#include <cuda_runtime.h>
#include <cuda_fp16.h>
#include <cstdint>

#define N_NODES 500000
#define N_EDGES 5000000
#define N_GRAPHS 5000
#define FEAT 7
#define STATE 16
#define ROUNDS 4

#define SCAN_CHUNK 1024
#define SCAN_T 256
#define SCAN_NB ((N_NODES + SCAN_CHUNK - 1) / SCAN_CHUNK)   // 489

// ---- scratch (__device__ globals; no allocs allowed) ----
__device__ __half g_state[N_NODES * STATE];    // fp16 state (16 MB)
__device__ __half g_msg_a[N_NODES * STATE];
__device__ __half g_msg_b[N_NODES * STATE];
__device__ int    g_cnt[N_NODES + 8];
__device__ int    g_fill[N_NODES + 8];
__device__ int    g_excl[N_NODES + 8];
__device__ int    g_bsum[SCAN_NB];
__device__ int    g_ptr[N_NODES + 8];
__device__ int    g_csr_src[N_EDGES];

// ---- 256-bit load/store helpers (sm_100+) ----
__device__ __forceinline__ void ldg256(const void* p, unsigned int* w) {
    asm volatile("ld.global.nc.v8.b32 {%0,%1,%2,%3,%4,%5,%6,%7}, [%8];"
                 : "=r"(w[0]), "=r"(w[1]), "=r"(w[2]), "=r"(w[3]),
                   "=r"(w[4]), "=r"(w[5]), "=r"(w[6]), "=r"(w[7])
                 : "l"(p));
}
__device__ __forceinline__ void stg256(void* p, const unsigned int* w) {
    asm volatile("st.global.v8.b32 [%0], {%1,%2,%3,%4,%5,%6,%7,%8};"
                 :: "l"(p),
                    "r"(w[0]), "r"(w[1]), "r"(w[2]), "r"(w[3]),
                    "r"(w[4]), "r"(w[5]), "r"(w[6]), "r"(w[7])
                 : "memory");
}

__device__ __forceinline__ void store_h16(__half* dst, const float* m) {
    unsigned int w[8];
#pragma unroll
    for (int v = 0; v < 8; v++) {
        __half2 hh = __floats2half2_rn(m[2 * v], m[2 * v + 1]);
        w[v] = *reinterpret_cast<unsigned int*>(&hh);
    }
    stg256(dst, w);
}

__device__ __forceinline__ void load_h16(const __half* src, float* f) {
    unsigned int w[8];
    ldg256(src, w);
#pragma unroll
    for (int v = 0; v < 8; v++) {
        __half2 hh = *reinterpret_cast<const __half2*>(&w[v]);
        float2 ff = __half22float2(hh);
        f[2 * v] = ff.x;
        f[2 * v + 1] = ff.y;
    }
}

__device__ __forceinline__ void acc_row8(const unsigned int* w, float* acc) {
#pragma unroll
    for (int v = 0; v < 8; v++) {
        __half2 hh = *reinterpret_cast<const __half2*>(&w[v]);
        float2 f = __half22float2(hh);
        acc[2 * v] += f.x;
        acc[2 * v + 1] += f.y;
    }
}

// ================= CSR build =================
__global__ void zero_cnt_kernel() {
    int i4 = (blockIdx.x * blockDim.x + threadIdx.x) * 4;
    if (i4 < N_NODES)
        *reinterpret_cast<int4*>(g_cnt + i4) = make_int4(0, 0, 0, 0);
}

// 8 edges/thread histogram (fire-and-forget REDs)
__global__ void hist_kernel(const int* __restrict__ ei) {
    int e8 = (blockIdx.x * blockDim.x + threadIdx.x) * 8;
    if (e8 >= N_EDGES) return;
    int4 d0 = __ldg(reinterpret_cast<const int4*>(ei + N_EDGES + e8));
    int4 d1 = __ldg(reinterpret_cast<const int4*>(ei + N_EDGES + e8 + 4));
    atomicAdd(&g_cnt[d0.x], 1);
    atomicAdd(&g_cnt[d0.y], 1);
    atomicAdd(&g_cnt[d0.z], 1);
    atomicAdd(&g_cnt[d0.w], 1);
    atomicAdd(&g_cnt[d1.x], 1);
    atomicAdd(&g_cnt[d1.y], 1);
    atomicAdd(&g_cnt[d1.z], 1);
    atomicAdd(&g_cnt[d1.w], 1);
}

__global__ void scan1_kernel() {
    __shared__ int sh[SCAN_T];
    int b = blockIdx.x, t = threadIdx.x;
    int base = b * SCAN_CHUNK + t * 4;
    int4 vv = (base < N_NODES) ? *reinterpret_cast<const int4*>(g_cnt + base)
                               : make_int4(0, 0, 0, 0);
    int v[4] = {vv.x, vv.y, vv.z, vv.w};
#pragma unroll
    for (int k = 0; k < 4; k++)
        if (base + k >= N_NODES) v[k] = 0;
    int s = v[0] + v[1] + v[2] + v[3];
    sh[t] = s;
    __syncthreads();
    for (int off = 1; off < SCAN_T; off <<= 1) {
        int x = (t >= off) ? sh[t - off] : 0;
        __syncthreads();
        sh[t] += x;
        __syncthreads();
    }
    int thread_excl = sh[t] - s;
    if (t == SCAN_T - 1) g_bsum[b] = sh[t];
    int4 ev;
    ev.x = thread_excl;
    ev.y = ev.x + v[0];
    ev.z = ev.y + v[1];
    ev.w = ev.z + v[2];
    if (base < N_NODES)
        *reinterpret_cast<int4*>(g_excl + base) = ev;
}

// fused: scan block sums locally (redundant per block), write ptr + fill
__global__ void scan3_kernel() {
    __shared__ int sb[512];
    int b = blockIdx.x, t = threadIdx.x;
    int orig = 0, orig2 = 0;
    if (t < SCAN_NB) orig = g_bsum[t];
    if (t + 256 < SCAN_NB) orig2 = g_bsum[t + 256];
    sb[t] = orig;
    sb[t + 256] = orig2;
    __syncthreads();
    for (int off = 1; off < 512; off <<= 1) {
        int x0 = (t >= off) ? sb[t - off] : 0;
        int x1 = (t + 256 >= off) ? sb[t + 256 - off] : 0;
        __syncthreads();
        sb[t] += x0;
        sb[t + 256] += x1;
        __syncthreads();
    }
    __shared__ int sexcl[512];
    sexcl[t] = sb[t] - orig;
    sexcl[t + 256] = sb[t + 256] - orig2;
    __syncthreads();

    int base = b * SCAN_CHUNK + t * 4;
    if (base < N_NODES) {
        int add = sexcl[base / SCAN_CHUNK];
        int4 e = *reinterpret_cast<const int4*>(g_excl + base);
        int4 p = make_int4(e.x + add, e.y + add, e.z + add, e.w + add);
        *reinterpret_cast<int4*>(g_ptr + base) = p;
        *reinterpret_cast<int4*>(g_fill + base) = p;
    }
    if (b == 0 && t == 0) g_ptr[N_NODES] = N_EDGES;
}

// 8 edges/thread scatter: atomic claims absolute slot, then write
__global__ void scatter_kernel(const int* __restrict__ ei) {
    int e8 = (blockIdx.x * blockDim.x + threadIdx.x) * 8;
    if (e8 >= N_EDGES) return;
    int4 s0 = __ldg(reinterpret_cast<const int4*>(ei + e8));
    int4 s1 = __ldg(reinterpret_cast<const int4*>(ei + e8 + 4));
    int4 d0 = __ldg(reinterpret_cast<const int4*>(ei + N_EDGES + e8));
    int4 d1 = __ldg(reinterpret_cast<const int4*>(ei + N_EDGES + e8 + 4));
    int p0 = atomicAdd(&g_fill[d0.x], 1);
    int p1 = atomicAdd(&g_fill[d0.y], 1);
    int p2 = atomicAdd(&g_fill[d0.z], 1);
    int p3 = atomicAdd(&g_fill[d0.w], 1);
    int p4 = atomicAdd(&g_fill[d1.x], 1);
    int p5 = atomicAdd(&g_fill[d1.y], 1);
    int p6 = atomicAdd(&g_fill[d1.z], 1);
    int p7 = atomicAdd(&g_fill[d1.w], 1);
    g_csr_src[p0] = s0.x;
    g_csr_src[p1] = s0.y;
    g_csr_src[p2] = s0.z;
    g_csr_src[p3] = s0.w;
    g_csr_src[p4] = s1.x;
    g_csr_src[p5] = s1.y;
    g_csr_src[p6] = s1.z;
    g_csr_src[p7] = s1.w;
}

// ============ input: state = relu(x@inW+b), msg0 = relu(state@msgW0+b0) ============
__global__ void input_kernel(const float* __restrict__ x,
                             const float* __restrict__ inW,
                             const float* __restrict__ inb,
                             const float* __restrict__ mW,
                             const float* __restrict__ mb,
                             const float* __restrict__ out_b,
                             float* __restrict__ out) {
    __shared__ float sIW[FEAT * STATE];
    __shared__ float sIb[STATE];
    __shared__ float sMW[STATE * STATE];
    __shared__ float sMb[STATE];
    int t = threadIdx.x;
    if (t < FEAT * STATE) sIW[t] = inW[t];
    if (t < STATE) { sIb[t] = inb[t]; sMb[t] = mb[t]; }
    if (t < STATE * STATE) sMW[t] = mW[t];
    __syncthreads();

    int i = blockIdx.x * blockDim.x + t;
    if (i < N_GRAPHS) out[i] = out_b[0];
    if (i >= N_NODES) return;

    float xi[FEAT];
#pragma unroll
    for (int k = 0; k < FEAT; k++) xi[k] = x[(size_t)i * FEAT + k];

    float st[STATE];
#pragma unroll
    for (int j = 0; j < STATE; j++) {
        float acc = sIb[j];
#pragma unroll
        for (int k = 0; k < FEAT; k++) acc = fmaf(xi[k], sIW[k * STATE + j], acc);
        st[j] = fmaxf(acc, 0.f);
    }
    store_h16(g_state + (size_t)i * STATE, st);

    float m[STATE];
#pragma unroll
    for (int j = 0; j < STATE; j++) {
        float acc = sMb[j];
#pragma unroll
        for (int k = 0; k < STATE; k++) acc = fmaf(st[k], sMW[k * STATE + j], acc);
        m[j] = fmaxf(acc, 0.f);
    }
    store_h16(g_msg_a + (size_t)i * STATE, m);
}

// ============ fused round: 1 thread/node, 256-bit gathers, prefetched indices ============
__global__ __launch_bounds__(256) void round_kernel(
                             const float* __restrict__ updW,
                             const float* __restrict__ updb,
                             const float* __restrict__ msgW,   // unused if last
                             const float* __restrict__ msgb,
                             const __half* __restrict__ msg_in,
                             __half* __restrict__ msg_out,
                             int last,
                             const int* __restrict__ batch,
                             const float* __restrict__ outW,
                             float* __restrict__ out) {
    __shared__ float sUW[STATE * STATE];
    __shared__ float sMW[STATE * STATE];
    __shared__ float sUb[STATE];
    __shared__ float sMb[STATE];
    __shared__ float sOW[STATE];
    int t = threadIdx.x;
    if (t < STATE * STATE) {
        sUW[t] = updW[t];
        sMW[t] = last ? 0.f : msgW[t];
    }
    if (t < STATE) {
        sUb[t] = updb[t];
        sMb[t] = last ? 0.f : msgb[t];
        sOW[t] = last ? outW[t] : 0.f;
    }
    __syncthreads();

    int node = blockIdx.x * blockDim.x + t;
    if (node >= N_NODES) return;

    int p0 = g_ptr[node];
    int p1 = g_ptr[node + 1];

    float acc[STATE];
#pragma unroll
    for (int k = 0; k < STATE; k++) acc[k] = 0.f;

    // software-pipelined gather: prefetch next 4 indices before consuming msgs
    int j = p0;
    int s0 = 0, s1 = 0, s2 = 0, s3 = 0;
    if (j + 4 <= p1) {
        s0 = __ldg(&g_csr_src[j + 0]);
        s1 = __ldg(&g_csr_src[j + 1]);
        s2 = __ldg(&g_csr_src[j + 2]);
        s3 = __ldg(&g_csr_src[j + 3]);
    }
    for (; j + 4 <= p1; j += 4) {
        unsigned int w0[8], w1[8], w2[8], w3[8];
        ldg256(msg_in + (size_t)s0 * STATE, w0);
        ldg256(msg_in + (size_t)s1 * STATE, w1);
        ldg256(msg_in + (size_t)s2 * STATE, w2);
        ldg256(msg_in + (size_t)s3 * STATE, w3);
        if (j + 8 <= p1) {          // prefetch next quad (overlaps msg loads)
            s0 = __ldg(&g_csr_src[j + 4]);
            s1 = __ldg(&g_csr_src[j + 5]);
            s2 = __ldg(&g_csr_src[j + 6]);
            s3 = __ldg(&g_csr_src[j + 7]);
        }
        acc_row8(w0, acc);
        acc_row8(w1, acc);
        acc_row8(w2, acc);
        acc_row8(w3, acc);
    }
    for (; j < p1; j++) {
        int s = __ldg(&g_csr_src[j]);
        unsigned int w[8];
        ldg256(msg_in + (size_t)s * STATE, w);
        acc_row8(w, acc);
    }

    // fp16 state load (one 32B op)
    float st[STATE];
    load_h16(g_state + (size_t)node * STATE, st);

    // state += relu(agg @ updW + updb)
#pragma unroll
    for (int jj = 0; jj < STATE; jj++) {
        float u = sUb[jj];
#pragma unroll
        for (int k = 0; k < STATE; k++) u = fmaf(acc[k], sUW[k * STATE + jj], u);
        st[jj] += fmaxf(u, 0.f);
    }

    if (!last) {
        store_h16(g_state + (size_t)node * STATE, st);
        float m[STATE];
#pragma unroll
        for (int jj = 0; jj < STATE; jj++) {
            float a2 = sMb[jj];
#pragma unroll
            for (int k = 0; k < STATE; k++) a2 = fmaf(st[k], sMW[k * STATE + jj], a2);
            m[jj] = fmaxf(a2, 0.f);
        }
        store_h16(msg_out + (size_t)node * STATE, m);
    } else {
        // readout with warp-segmented aggregation (batch is sorted)
        float dot = 0.f;
#pragma unroll
        for (int k = 0; k < STATE; k++) dot = fmaf(st[k], sOW[k], dot);
        int b = batch[node];

        unsigned mask = __activemask();       // active lanes are a prefix
        int cnt = __popc(mask);
        int lane = t & 31;
#pragma unroll
        for (int off = 1; off < 32; off <<= 1) {
            float d2 = __shfl_down_sync(mask, dot, off);
            int b2   = __shfl_down_sync(mask, b, off);
            if (lane + off < cnt && b2 == b) dot += d2;
        }
        int bprev = __shfl_up_sync(mask, b, 1);
        if (lane == 0 || bprev != b)
            atomicAdd(&out[b], dot);
    }
}

extern "C" void kernel_launch(void* const* d_in, const int* in_sizes, int n_in,
                              void* d_out, int out_size) {
    const float* x     = (const float*)d_in[0];
    const int*   ei    = (const int*)d_in[1];
    const int*   batch = (const int*)d_in[2];
    const float* in_W  = (const float*)d_in[3];
    const float* in_b  = (const float*)d_in[4];
    const float* msg_W = (const float*)d_in[5];
    const float* msg_b = (const float*)d_in[6];
    const float* upd_W = (const float*)d_in[7];
    const float* upd_b = (const float*)d_in[8];
    const float* out_W = (const float*)d_in[9];
    const float* out_b = (const float*)d_in[10];
    float* out = (float*)d_out;

    static cudaStream_t s2 = nullptr;
    static cudaEvent_t evFork = nullptr, evJoin = nullptr;
    if (s2 == nullptr) {
        cudaStreamCreateWithFlags(&s2, cudaStreamNonBlocking);
        cudaEventCreateWithFlags(&evFork, cudaEventDisableTiming);
        cudaEventCreateWithFlags(&evJoin, cudaEventDisableTiming);
    }

    const int TB = 256;
    int node_blocks  = (N_NODES + TB - 1) / TB;
    int node4_blocks = (N_NODES / 4 + TB - 1) / TB;
    int edge8_blocks = (N_EDGES / 8 + TB - 1) / TB;

    // fork: input (+ out init) runs concurrently with the CSR build
    cudaEventRecord(evFork, 0);
    cudaStreamWaitEvent(s2, evFork, 0);
    input_kernel<<<node_blocks, TB, 0, s2>>>(x, in_W, in_b, msg_W, msg_b, out_b, out);
    cudaEventRecord(evJoin, s2);

    // CSR build chain on the main stream
    zero_cnt_kernel<<<node4_blocks, TB>>>();
    hist_kernel<<<edge8_blocks, TB>>>(ei);
    scan1_kernel<<<SCAN_NB, SCAN_T>>>();
    scan3_kernel<<<SCAN_NB, SCAN_T>>>();
    scatter_kernel<<<edge8_blocks, TB>>>(ei);

    cudaStreamWaitEvent(0, evJoin, 0);

    void* pa; void* pb;
    cudaGetSymbolAddress(&pa, g_msg_a);
    cudaGetSymbolAddress(&pb, g_msg_b);
    __half* bufs[2] = {(__half*)pa, (__half*)pb};

    for (int r = 0; r < ROUNDS; r++) {
        int last = (r == ROUNDS - 1);
        const float* mW = last ? msg_W : (msg_W + (r + 1) * STATE * STATE);
        const float* mb = last ? msg_b : (msg_b + (r + 1) * STATE);
        round_kernel<<<node_blocks, TB>>>(
            upd_W + r * STATE * STATE, upd_b + r * STATE,
            mW, mb,
            bufs[r & 1], bufs[(r + 1) & 1],
            last, batch, out_W, out);
    }
}

// round 17
// speedup vs baseline: 1.1199x; 1.0017x over previous
#include <cuda_runtime.h>
#include <cuda_fp16.h>
#include <cstdint>

#define N_NODES 500000
#define N_EDGES 5000000
#define N_GRAPHS 5000
#define FEAT 7
#define STATE 16
#define ROUNDS 4

#define SCAN_CHUNK 1024
#define SCAN_T 256
#define SCAN_NB ((N_NODES + SCAN_CHUNK - 1) / SCAN_CHUNK)   // 489

// ---- scratch (__device__ globals; no allocs allowed) ----
// NOTE: g_cnt is zero at module load and is re-zeroed by scan1 after each use,
// so no explicit zeroing kernel is needed (replay-safe invariant).
__device__ __half g_state[N_NODES * STATE];    // fp16 state (16 MB)
__device__ __half g_msg_a[N_NODES * STATE];
__device__ __half g_msg_b[N_NODES * STATE];
__device__ int    g_cnt[N_NODES + 8];
__device__ int    g_fill[N_NODES + 8];
__device__ int    g_excl[N_NODES + 8];
__device__ int    g_bsum[SCAN_NB];
__device__ int    g_ptr[N_NODES + 8];
__device__ int    g_csr_src[N_EDGES];

// ---- 256-bit load/store helpers (sm_100+) ----
__device__ __forceinline__ void ldg256(const void* p, unsigned int* w) {
    asm volatile("ld.global.nc.v8.b32 {%0,%1,%2,%3,%4,%5,%6,%7}, [%8];"
                 : "=r"(w[0]), "=r"(w[1]), "=r"(w[2]), "=r"(w[3]),
                   "=r"(w[4]), "=r"(w[5]), "=r"(w[6]), "=r"(w[7])
                 : "l"(p));
}
__device__ __forceinline__ void stg256(void* p, const unsigned int* w) {
    asm volatile("st.global.v8.b32 [%0], {%1,%2,%3,%4,%5,%6,%7,%8};"
                 :: "l"(p),
                    "r"(w[0]), "r"(w[1]), "r"(w[2]), "r"(w[3]),
                    "r"(w[4]), "r"(w[5]), "r"(w[6]), "r"(w[7])
                 : "memory");
}

__device__ __forceinline__ void store_h16(__half* dst, const float* m) {
    unsigned int w[8];
#pragma unroll
    for (int v = 0; v < 8; v++) {
        __half2 hh = __floats2half2_rn(m[2 * v], m[2 * v + 1]);
        w[v] = *reinterpret_cast<unsigned int*>(&hh);
    }
    stg256(dst, w);
}

__device__ __forceinline__ void load_h16(const __half* src, float* f) {
    unsigned int w[8];
    ldg256(src, w);
#pragma unroll
    for (int v = 0; v < 8; v++) {
        __half2 hh = *reinterpret_cast<const __half2*>(&w[v]);
        float2 ff = __half22float2(hh);
        f[2 * v] = ff.x;
        f[2 * v + 1] = ff.y;
    }
}

__device__ __forceinline__ void acc_row8(const unsigned int* w, float* acc) {
#pragma unroll
    for (int v = 0; v < 8; v++) {
        __half2 hh = *reinterpret_cast<const __half2*>(&w[v]);
        float2 f = __half22float2(hh);
        acc[2 * v] += f.x;
        acc[2 * v + 1] += f.y;
    }
}

// ================= CSR build =================
// 8 edges/thread histogram (fire-and-forget REDs); g_cnt arrives zeroed
__global__ void hist_kernel(const int* __restrict__ ei) {
    int e8 = (blockIdx.x * blockDim.x + threadIdx.x) * 8;
    if (e8 >= N_EDGES) return;
    int4 d0 = __ldg(reinterpret_cast<const int4*>(ei + N_EDGES + e8));
    int4 d1 = __ldg(reinterpret_cast<const int4*>(ei + N_EDGES + e8 + 4));
    atomicAdd(&g_cnt[d0.x], 1);
    atomicAdd(&g_cnt[d0.y], 1);
    atomicAdd(&g_cnt[d0.z], 1);
    atomicAdd(&g_cnt[d0.w], 1);
    atomicAdd(&g_cnt[d1.x], 1);
    atomicAdd(&g_cnt[d1.y], 1);
    atomicAdd(&g_cnt[d1.z], 1);
    atomicAdd(&g_cnt[d1.w], 1);
}

// block-local exclusive scan; also re-zeroes g_cnt for the next replay
__global__ void scan1_kernel() {
    __shared__ int sh[SCAN_T];
    int b = blockIdx.x, t = threadIdx.x;
    int base = b * SCAN_CHUNK + t * 4;
    int4 vv = (base < N_NODES) ? *reinterpret_cast<const int4*>(g_cnt + base)
                               : make_int4(0, 0, 0, 0);
    if (base < N_NODES)    // self-clean: next launch's hist needs zeros
        *reinterpret_cast<int4*>(g_cnt + base) = make_int4(0, 0, 0, 0);
    int v[4] = {vv.x, vv.y, vv.z, vv.w};
#pragma unroll
    for (int k = 0; k < 4; k++)
        if (base + k >= N_NODES) v[k] = 0;
    int s = v[0] + v[1] + v[2] + v[3];
    sh[t] = s;
    __syncthreads();
    for (int off = 1; off < SCAN_T; off <<= 1) {
        int x = (t >= off) ? sh[t - off] : 0;
        __syncthreads();
        sh[t] += x;
        __syncthreads();
    }
    int thread_excl = sh[t] - s;
    if (t == SCAN_T - 1) g_bsum[b] = sh[t];
    int4 ev;
    ev.x = thread_excl;
    ev.y = ev.x + v[0];
    ev.z = ev.y + v[1];
    ev.w = ev.z + v[2];
    if (base < N_NODES)
        *reinterpret_cast<int4*>(g_excl + base) = ev;
}

// fused: scan block sums locally (redundant per block), write ptr + fill
__global__ void scan3_kernel() {
    __shared__ int sb[512];
    int b = blockIdx.x, t = threadIdx.x;
    int orig = 0, orig2 = 0;
    if (t < SCAN_NB) orig = g_bsum[t];
    if (t + 256 < SCAN_NB) orig2 = g_bsum[t + 256];
    sb[t] = orig;
    sb[t + 256] = orig2;
    __syncthreads();
    for (int off = 1; off < 512; off <<= 1) {
        int x0 = (t >= off) ? sb[t - off] : 0;
        int x1 = (t + 256 >= off) ? sb[t + 256 - off] : 0;
        __syncthreads();
        sb[t] += x0;
        sb[t + 256] += x1;
        __syncthreads();
    }
    __shared__ int sexcl[512];
    sexcl[t] = sb[t] - orig;
    sexcl[t + 256] = sb[t + 256] - orig2;
    __syncthreads();

    int base = b * SCAN_CHUNK + t * 4;
    if (base < N_NODES) {
        int add = sexcl[base / SCAN_CHUNK];
        int4 e = *reinterpret_cast<const int4*>(g_excl + base);
        int4 p = make_int4(e.x + add, e.y + add, e.z + add, e.w + add);
        *reinterpret_cast<int4*>(g_ptr + base) = p;
        *reinterpret_cast<int4*>(g_fill + base) = p;
    }
    if (b == 0 && t == 0) g_ptr[N_NODES] = N_EDGES;
}

// 8 edges/thread scatter: atomic claims absolute slot, then write
__global__ void scatter_kernel(const int* __restrict__ ei) {
    int e8 = (blockIdx.x * blockDim.x + threadIdx.x) * 8;
    if (e8 >= N_EDGES) return;
    int4 s0 = __ldg(reinterpret_cast<const int4*>(ei + e8));
    int4 s1 = __ldg(reinterpret_cast<const int4*>(ei + e8 + 4));
    int4 d0 = __ldg(reinterpret_cast<const int4*>(ei + N_EDGES + e8));
    int4 d1 = __ldg(reinterpret_cast<const int4*>(ei + N_EDGES + e8 + 4));
    int p0 = atomicAdd(&g_fill[d0.x], 1);
    int p1 = atomicAdd(&g_fill[d0.y], 1);
    int p2 = atomicAdd(&g_fill[d0.z], 1);
    int p3 = atomicAdd(&g_fill[d0.w], 1);
    int p4 = atomicAdd(&g_fill[d1.x], 1);
    int p5 = atomicAdd(&g_fill[d1.y], 1);
    int p6 = atomicAdd(&g_fill[d1.z], 1);
    int p7 = atomicAdd(&g_fill[d1.w], 1);
    g_csr_src[p0] = s0.x;
    g_csr_src[p1] = s0.y;
    g_csr_src[p2] = s0.z;
    g_csr_src[p3] = s0.w;
    g_csr_src[p4] = s1.x;
    g_csr_src[p5] = s1.y;
    g_csr_src[p6] = s1.z;
    g_csr_src[p7] = s1.w;
}

// ============ input: state = relu(x@inW+b), msg0 = relu(state@msgW0+b0) ============
__global__ void input_kernel(const float* __restrict__ x,
                             const float* __restrict__ inW,
                             const float* __restrict__ inb,
                             const float* __restrict__ mW,
                             const float* __restrict__ mb,
                             const float* __restrict__ out_b,
                             float* __restrict__ out) {
    __shared__ float sIW[FEAT * STATE];
    __shared__ float sIb[STATE];
    __shared__ float sMW[STATE * STATE];
    __shared__ float sMb[STATE];
    int t = threadIdx.x;
    if (t < FEAT * STATE) sIW[t] = inW[t];
    if (t < STATE) { sIb[t] = inb[t]; sMb[t] = mb[t]; }
    if (t < STATE * STATE) sMW[t] = mW[t];
    __syncthreads();

    int i = blockIdx.x * blockDim.x + t;
    if (i < N_GRAPHS) out[i] = out_b[0];
    if (i >= N_NODES) return;

    float xi[FEAT];
#pragma unroll
    for (int k = 0; k < FEAT; k++) xi[k] = x[(size_t)i * FEAT + k];

    float st[STATE];
#pragma unroll
    for (int j = 0; j < STATE; j++) {
        float acc = sIb[j];
#pragma unroll
        for (int k = 0; k < FEAT; k++) acc = fmaf(xi[k], sIW[k * STATE + j], acc);
        st[j] = fmaxf(acc, 0.f);
    }
    store_h16(g_state + (size_t)i * STATE, st);

    float m[STATE];
#pragma unroll
    for (int j = 0; j < STATE; j++) {
        float acc = sMb[j];
#pragma unroll
        for (int k = 0; k < STATE; k++) acc = fmaf(st[k], sMW[k * STATE + j], acc);
        m[j] = fmaxf(acc, 0.f);
    }
    store_h16(g_msg_a + (size_t)i * STATE, m);
}

// ============ fused round: 1 thread/node, 256-bit gathers, prefetched indices ============
__global__ __launch_bounds__(256) void round_kernel(
                             const float* __restrict__ updW,
                             const float* __restrict__ updb,
                             const float* __restrict__ msgW,   // unused if last
                             const float* __restrict__ msgb,
                             const __half* __restrict__ msg_in,
                             __half* __restrict__ msg_out,
                             int last,
                             const int* __restrict__ batch,
                             const float* __restrict__ outW,
                             float* __restrict__ out) {
    __shared__ float sUW[STATE * STATE];
    __shared__ float sMW[STATE * STATE];
    __shared__ float sUb[STATE];
    __shared__ float sMb[STATE];
    __shared__ float sOW[STATE];
    int t = threadIdx.x;
    if (t < STATE * STATE) {
        sUW[t] = updW[t];
        sMW[t] = last ? 0.f : msgW[t];
    }
    if (t < STATE) {
        sUb[t] = updb[t];
        sMb[t] = last ? 0.f : msgb[t];
        sOW[t] = last ? outW[t] : 0.f;
    }
    __syncthreads();

    int node = blockIdx.x * blockDim.x + t;
    if (node >= N_NODES) return;

    int p0 = g_ptr[node];
    int p1 = g_ptr[node + 1];

    float acc[STATE];
#pragma unroll
    for (int k = 0; k < STATE; k++) acc[k] = 0.f;

    // software-pipelined gather: prefetch next 4 indices before consuming msgs
    int j = p0;
    int s0 = 0, s1 = 0, s2 = 0, s3 = 0;
    if (j + 4 <= p1) {
        s0 = __ldg(&g_csr_src[j + 0]);
        s1 = __ldg(&g_csr_src[j + 1]);
        s2 = __ldg(&g_csr_src[j + 2]);
        s3 = __ldg(&g_csr_src[j + 3]);
    }
    for (; j + 4 <= p1; j += 4) {
        unsigned int w0[8], w1[8], w2[8], w3[8];
        ldg256(msg_in + (size_t)s0 * STATE, w0);
        ldg256(msg_in + (size_t)s1 * STATE, w1);
        ldg256(msg_in + (size_t)s2 * STATE, w2);
        ldg256(msg_in + (size_t)s3 * STATE, w3);
        if (j + 8 <= p1) {          // prefetch next quad (overlaps msg loads)
            s0 = __ldg(&g_csr_src[j + 4]);
            s1 = __ldg(&g_csr_src[j + 5]);
            s2 = __ldg(&g_csr_src[j + 6]);
            s3 = __ldg(&g_csr_src[j + 7]);
        }
        acc_row8(w0, acc);
        acc_row8(w1, acc);
        acc_row8(w2, acc);
        acc_row8(w3, acc);
    }
    for (; j < p1; j++) {
        int s = __ldg(&g_csr_src[j]);
        unsigned int w[8];
        ldg256(msg_in + (size_t)s * STATE, w);
        acc_row8(w, acc);
    }

    // fp16 state load (one 32B op)
    float st[STATE];
    load_h16(g_state + (size_t)node * STATE, st);

    // state += relu(agg @ updW + updb)
#pragma unroll
    for (int jj = 0; jj < STATE; jj++) {
        float u = sUb[jj];
#pragma unroll
        for (int k = 0; k < STATE; k++) u = fmaf(acc[k], sUW[k * STATE + jj], u);
        st[jj] += fmaxf(u, 0.f);
    }

    if (!last) {
        store_h16(g_state + (size_t)node * STATE, st);
        float m[STATE];
#pragma unroll
        for (int jj = 0; jj < STATE; jj++) {
            float a2 = sMb[jj];
#pragma unroll
            for (int k = 0; k < STATE; k++) a2 = fmaf(st[k], sMW[k * STATE + jj], a2);
            m[jj] = fmaxf(a2, 0.f);
        }
        store_h16(msg_out + (size_t)node * STATE, m);
    } else {
        // readout with warp-segmented aggregation (batch is sorted)
        float dot = 0.f;
#pragma unroll
        for (int k = 0; k < STATE; k++) dot = fmaf(st[k], sOW[k], dot);
        int b = batch[node];

        unsigned mask = __activemask();       // active lanes are a prefix
        int cnt = __popc(mask);
        int lane = t & 31;
#pragma unroll
        for (int off = 1; off < 32; off <<= 1) {
            float d2 = __shfl_down_sync(mask, dot, off);
            int b2   = __shfl_down_sync(mask, b, off);
            if (lane + off < cnt && b2 == b) dot += d2;
        }
        int bprev = __shfl_up_sync(mask, b, 1);
        if (lane == 0 || bprev != b)
            atomicAdd(&out[b], dot);
    }
}

extern "C" void kernel_launch(void* const* d_in, const int* in_sizes, int n_in,
                              void* d_out, int out_size) {
    const float* x     = (const float*)d_in[0];
    const int*   ei    = (const int*)d_in[1];
    const int*   batch = (const int*)d_in[2];
    const float* in_W  = (const float*)d_in[3];
    const float* in_b  = (const float*)d_in[4];
    const float* msg_W = (const float*)d_in[5];
    const float* msg_b = (const float*)d_in[6];
    const float* upd_W = (const float*)d_in[7];
    const float* upd_b = (const float*)d_in[8];
    const float* out_W = (const float*)d_in[9];
    const float* out_b = (const float*)d_in[10];
    float* out = (float*)d_out;

    static cudaStream_t s2 = nullptr;
    static cudaEvent_t evFork = nullptr, evJoin = nullptr;
    if (s2 == nullptr) {
        cudaStreamCreateWithFlags(&s2, cudaStreamNonBlocking);
        cudaEventCreateWithFlags(&evFork, cudaEventDisableTiming);
        cudaEventCreateWithFlags(&evJoin, cudaEventDisableTiming);
    }

    const int TB = 256;
    int node_blocks  = (N_NODES + TB - 1) / TB;
    int edge8_blocks = (N_EDGES / 8 + TB - 1) / TB;

    // fork: input (+ out init) runs concurrently with the CSR build
    cudaEventRecord(evFork, 0);
    cudaStreamWaitEvent(s2, evFork, 0);
    input_kernel<<<node_blocks, TB, 0, s2>>>(x, in_W, in_b, msg_W, msg_b, out_b, out);
    cudaEventRecord(evJoin, s2);

    // CSR build chain on the main stream (g_cnt pre-zeroed: module load / scan1 self-clean)
    hist_kernel<<<edge8_blocks, TB>>>(ei);
    scan1_kernel<<<SCAN_NB, SCAN_T>>>();
    scan3_kernel<<<SCAN_NB, SCAN_T>>>();
    scatter_kernel<<<edge8_blocks, TB>>>(ei);

    cudaStreamWaitEvent(0, evJoin, 0);

    void* pa; void* pb;
    cudaGetSymbolAddress(&pa, g_msg_a);
    cudaGetSymbolAddress(&pb, g_msg_b);
    __half* bufs[2] = {(__half*)pa, (__half*)pb};

    for (int r = 0; r < ROUNDS; r++) {
        int last = (r == ROUNDS - 1);
        const float* mW = last ? msg_W : (msg_W + (r + 1) * STATE * STATE);
        const float* mb = last ? msg_b : (msg_b + (r + 1) * STATE);
        round_kernel<<<node_blocks, TB>>>(
            upd_W + r * STATE * STATE, upd_b + r * STATE,
            mW, mb,
            bufs[r & 1], bufs[(r + 1) & 1],
            last, batch, out_W, out);
    }
}